// round 1
// baseline (speedup 1.0000x reference)
#include <cuda_runtime.h>

#define TW 32
#define TH 8
#define NTHR 256
#define C 16
#define F 48            // 3*C features
#define HID 128
#define HW 512
#define TPW (TW + 2)
#define TPH (TH + 2)

// smem layout (floats):
//  xs   : C * TPH * TPW           = 16*10*34 = 5440
//  w0s  : HID * F                 = 6144
//  w1ts : HID * 16  (transposed)  = 2048
//  b0s  : HID                     = 128
#define SM_XS    0
#define SM_W0    (SM_XS + C * TPH * TPW)
#define SM_W1T   (SM_W0 + HID * F)
#define SM_B0    (SM_W1T + HID * 16)
#define SM_TOTAL (SM_B0 + HID)           // 13760 floats = 55040 bytes

__global__ __launch_bounds__(NTHR, 2)
void ca_kernel(const float* __restrict__ x,
               const float* __restrict__ w0,
               const float* __restrict__ b0,
               const float* __restrict__ w1,
               const float* __restrict__ rand_u,
               float* __restrict__ out)
{
    extern __shared__ float smem[];
    float* xs   = smem + SM_XS;
    float* w0s  = smem + SM_W0;
    float* w1ts = smem + SM_W1T;
    float* b0s  = smem + SM_B0;

    const int tid = threadIdx.x;
    const int tx  = tid & (TW - 1);
    const int ty  = tid / TW;
    const int gw0 = blockIdx.x * TW;
    const int gh0 = blockIdx.y * TH;
    const int b   = blockIdx.z;

    // ---- stage weights ----
    for (int i = tid; i < HID * F; i += NTHR) w0s[i] = w0[i];
    // w1 is [C=16][HID=128]; transpose to [HID][16] so per-o reads are contiguous
    for (int i = tid; i < HID * 16; i += NTHR) {
        int o = i >> 4, k = i & 15;
        w1ts[i] = w1[k * HID + o];
    }
    if (tid < HID) b0s[tid] = b0[tid];

    // ---- stage x tile with halo (zero pad) ----
    for (int i = tid; i < C * TPH * TPW; i += NTHR) {
        int c  = i / (TPH * TPW);
        int r  = i % (TPH * TPW);
        int hy = r / TPW;
        int hx = r % TPW;
        int gh = gh0 + hy - 1;
        int gwp = gw0 + hx - 1;
        float v = 0.f;
        if (gh >= 0 && gh < HW && gwp >= 0 && gwp < HW)
            v = x[(((size_t)b * C + c) * HW + gh) * HW + gwp];
        xs[i] = v;
    }
    __syncthreads();

    // ---- per-pixel features: y = [x_c, gradx_c, grady_c] ----
    float y[F];
    #pragma unroll
    for (int c = 0; c < C; c++) {
        const float* p = xs + c * (TPH * TPW) + ty * TPW + tx;  // top-left of 3x3
        float a00 = p[0],         a01 = p[1],          a02 = p[2];
        float a10 = p[TPW],       a11 = p[TPW + 1],    a12 = p[TPW + 2];
        float a20 = p[2 * TPW],   a21 = p[2 * TPW + 1], a22 = p[2 * TPW + 2];
        y[c]      = a11;
        // cross-correlation with sobel_x = [[-1,0,1],[-2,0,2],[-1,0,1]]
        y[16 + c] = (a02 - a00) + 2.f * (a12 - a10) + (a22 - a20);
        // sobel_y = sobel_x^T
        y[32 + c] = (a20 - a00) + 2.f * (a21 - a01) + (a22 - a02);
    }

    // ---- MLP: h = relu(w0 . y + b0); upd = w1 . h ----
    float upd[16];
    #pragma unroll
    for (int k = 0; k < 16; k++) upd[k] = 0.f;

    #pragma unroll 4
    for (int o = 0; o < HID; o++) {
        float acc = b0s[o];
        const float4* wrow = (const float4*)(w0s + o * F);
        #pragma unroll
        for (int j = 0; j < F / 4; j++) {
            float4 wv = wrow[j];
            acc += wv.x * y[4 * j]     + wv.y * y[4 * j + 1]
                 + wv.z * y[4 * j + 2] + wv.w * y[4 * j + 3];
        }
        acc = fmaxf(acc, 0.f);
        const float4* w1row = (const float4*)(w1ts + o * 16);
        #pragma unroll
        for (int j = 0; j < 4; j++) {
            float4 wv = w1row[j];
            upd[4 * j]     += acc * wv.x;
            upd[4 * j + 1] += acc * wv.y;
            upd[4 * j + 2] += acc * wv.z;
            upd[4 * j + 3] += acc * wv.w;
        }
    }

    // ---- masked residual write ----
    const int gh = gh0 + ty;
    const int gwp = gw0 + tx;
    float m = (rand_u[((size_t)b * HW + gh) * HW + gwp] > 0.5f) ? 1.f : 0.f;
    #pragma unroll
    for (int k = 0; k < 16; k++) {
        size_t idx = (((size_t)b * C + k) * HW + gh) * HW + gwp;
        out[idx] = y[k] + upd[k] * m;   // y[k] is the center x value
    }
}

extern "C" void kernel_launch(void* const* d_in, const int* in_sizes, int n_in,
                              void* d_out, int out_size)
{
    const float* x      = (const float*)d_in[0];
    const float* w0     = (const float*)d_in[1];
    const float* b0     = (const float*)d_in[2];
    const float* w1     = (const float*)d_in[3];
    const float* rand_u = (const float*)d_in[4];
    float* out = (float*)d_out;

    const int smem_bytes = SM_TOTAL * sizeof(float);  // 55040 B > 48K default
    cudaFuncSetAttribute(ca_kernel, cudaFuncAttributeMaxDynamicSharedMemorySize,
                         smem_bytes);

    dim3 grid(HW / TW, HW / TH, 4);
    ca_kernel<<<grid, NTHR, smem_bytes>>>(x, w0, b0, w1, rand_u, out);
}

// round 4
// speedup vs baseline: 2.2640x; 2.2640x over previous
#include <cuda_runtime.h>
#include <cstdint>

#define HW   512
#define NTHR 256
#define TPW  34
#define TPH  6
#define TILES_PER_CTA 8
#define N_TILES 8192            // 4 batches * 16 * 128 tiles of 32x4

// smem layout (float offsets)
#define XS_OFF 0                // [16][6][34]           = 3264
#define YS_STR 136
#define YS_OFF 3264             // [48][136]             = 6528
#define H_STR  72
#define H_OFF  (YS_OFF + 6528)  // [128][72]             = 9216
#define W0_OFF (H_OFF + 9216)   // [128][48]             = 6144
#define W1_STR 132
#define W1_OFF (W0_OFF + 6144)  // [16][132]             = 2112
#define B0_OFF (W1_OFF + 2112)  // 128
#define MS_OFF (B0_OFF + 128)   // 128
#define SM_FLOATS (MS_OFF + 128)       // 27520 floats = 110080 B

__device__ __forceinline__ float tf32f(float f) {
    uint32_t u;
    asm("cvt.rna.tf32.f32 %0, %1;" : "=r"(u) : "f"(f));
    return __uint_as_float(u);
}

// D += A(16x8) * B(8x8), tf32 inputs (as b32 regs), f32 accumulate
__device__ __forceinline__ void mma8(float* d, const float* a, float b0, float b1) {
    asm("mma.sync.aligned.m16n8k8.row.col.f32.tf32.tf32.f32 "
        "{%0,%1,%2,%3}, {%4,%5,%6,%7}, {%8,%9}, {%0,%1,%2,%3};"
        : "+f"(d[0]), "+f"(d[1]), "+f"(d[2]), "+f"(d[3])
        : "r"(__float_as_uint(a[0])), "r"(__float_as_uint(a[1])),
          "r"(__float_as_uint(a[2])), "r"(__float_as_uint(a[3])),
          "r"(__float_as_uint(b0)), "r"(__float_as_uint(b1)));
}

__global__ __launch_bounds__(NTHR, 2)
void ca_mma_kernel(const float* __restrict__ x,
                   const float* __restrict__ w0,
                   const float* __restrict__ b0,
                   const float* __restrict__ w1,
                   const float* __restrict__ rand_u,
                   float* __restrict__ out)
{
    extern __shared__ float sm[];
    float* xs  = sm + XS_OFF;
    float* ys  = sm + YS_OFF;
    float* Hs  = sm + H_OFF;
    float* w0s = sm + W0_OFF;
    float* w1s = sm + W1_OFF;
    float* b0s = sm + B0_OFF;
    float* ms  = sm + MS_OFF;

    const int tid  = threadIdx.x;
    const int lane = tid & 31;
    const int wid  = tid >> 5;
    const int g    = lane >> 2;   // groupID
    const int t    = lane & 3;    // thread-in-group

    // ---- stage weights (tf32-rounded) ----
    for (int i = tid; i < 128 * 48; i += NTHR) w0s[i] = tf32f(w0[i]);
    for (int i = tid; i < 16 * 128; i += NTHR) {
        int r = i >> 7, c = i & 127;
        w1s[r * W1_STR + c] = tf32f(w1[i]);
    }
    if (tid < 128) b0s[tid] = b0[tid];
    __syncthreads();

    // ---- persistent W0 A-fragments: warp wid owns hid rows [16*wid, 16*wid+16) ----
    float a1f[6][4];
    {
        const int r0 = 16 * wid + g;
        #pragma unroll
        for (int s = 0; s < 6; s++) {
            a1f[s][0] = w0s[r0 * 48 + 8 * s + t];
            a1f[s][1] = w0s[(r0 + 8) * 48 + 8 * s + t];
            a1f[s][2] = w0s[r0 * 48 + 8 * s + t + 4];
            a1f[s][3] = w0s[(r0 + 8) * 48 + 8 * s + t + 4];
        }
    }
    const float bias0 = b0s[16 * wid + g];
    const float bias1 = b0s[16 * wid + g + 8];

    const int px_  = tid & 127;          // feature pixel for this thread
    const int fsel = tid >> 7;           // which 8 channels
    const int fpy  = px_ >> 5, fpx = px_ & 31;

    const int tile0 = blockIdx.x * TILES_PER_CTA;
    for (int it = 0; it < TILES_PER_CTA; ++it) {
        const int tile = tile0 + it;
        const int b    = tile >> 11;
        const int rem  = tile & 2047;
        const int gh0  = (rem >> 4) * 4;
        const int gw0  = (rem & 15) * 32;

        __syncthreads();   // protect xs/ms from previous iteration's readers

        // ---- halo load (zero pad) ----
        for (int i = tid; i < 16 * TPH * TPW; i += NTHR) {
            int c  = i / (TPH * TPW);
            int r  = i % (TPH * TPW);
            int hy = r / TPW, hx = r % TPW;
            int gh = gh0 + hy - 1, gw = gw0 + hx - 1;
            float v = 0.f;
            if (gh >= 0 && gh < HW && gw >= 0 && gw < HW)
                v = x[((size_t)(b * 16 + c) << 18) + (gh << 9) + gw];
            xs[i] = v;
        }
        if (tid < 128) {
            int gh = gh0 + (tid >> 5), gw = gw0 + (tid & 31);
            ms[tid] = rand_u[((size_t)b << 18) + (gh << 9) + gw] > 0.5f ? 1.f : 0.f;
        }
        __syncthreads();

        // ---- features: this thread does 8 channels for pixel px_ ----
        {
            const int cb = fsel * 8;
            #pragma unroll
            for (int c = 0; c < 8; c++) {
                const float* p = xs + (cb + c) * (TPH * TPW) + fpy * TPW + fpx;
                float a00 = p[0],       a01 = p[1],           a02 = p[2];
                float a10 = p[TPW],     a11 = p[TPW + 1],     a12 = p[TPW + 2];
                float a20 = p[2*TPW],   a21 = p[2*TPW + 1],   a22 = p[2*TPW + 2];
                float gx = (a02 - a00) + 2.f * (a12 - a10) + (a22 - a20);
                float gy = (a20 - a00) + 2.f * (a21 - a01) + (a22 - a02);
                ys[(cb + c) * YS_STR + px_]      = tf32f(a11);
                ys[(16 + cb + c) * YS_STR + px_] = tf32f(gx);
                ys[(32 + cb + c) * YS_STR + px_] = tf32f(gy);
            }
        }
        __syncthreads();

        // ---- two 64-pixel GEMM passes ----
        #pragma unroll 1
        for (int sub = 0; sub < 2; sub++) {
            const int pxb = sub * 64;

            // GEMM1: D1[16 hid rows of this warp][64 px] = W0 * Y  (+bias)
            float acc[8][4];
            #pragma unroll
            for (int j = 0; j < 8; j++) {
                acc[j][0] = bias0; acc[j][1] = bias0;
                acc[j][2] = bias1; acc[j][3] = bias1;
            }
            #pragma unroll
            for (int s = 0; s < 6; s++) {
                const float* yb0 = ys + (8 * s + t) * YS_STR + pxb + g;
                const float* yb1 = ys + (8 * s + t + 4) * YS_STR + pxb + g;
                #pragma unroll
                for (int j = 0; j < 8; j++)
                    mma8(acc[j], a1f[s], yb0[8 * j], yb1[8 * j]);
            }

            __syncthreads();   // everyone's GEMM2 reads of previous chunk's H are done

            // relu -> tf32 -> H[hid][64]
            {
                const int hr = 16 * wid + g;
                #pragma unroll
                for (int j = 0; j < 8; j++) {
                    int cc = 8 * j + 2 * t;
                    Hs[hr * H_STR + cc]           = tf32f(fmaxf(acc[j][0], 0.f));
                    Hs[hr * H_STR + cc + 1]       = tf32f(fmaxf(acc[j][1], 0.f));
                    Hs[(hr + 8) * H_STR + cc]     = tf32f(fmaxf(acc[j][2], 0.f));
                    Hs[(hr + 8) * H_STR + cc + 1] = tf32f(fmaxf(acc[j][3], 0.f));
                }
            }
            __syncthreads();   // H ready

            // GEMM2: D2[16 ch][8 px of this warp] = W1 * H
            float acc2[4] = {0.f, 0.f, 0.f, 0.f};
            #pragma unroll
            for (int s = 0; s < 16; s++) {
                float aa[4];
                aa[0] = w1s[g * W1_STR + 8 * s + t];
                aa[1] = w1s[(g + 8) * W1_STR + 8 * s + t];
                aa[2] = w1s[g * W1_STR + 8 * s + t + 4];
                aa[3] = w1s[(g + 8) * W1_STR + 8 * s + t + 4];
                float bb0 = Hs[(8 * s + t) * H_STR + 8 * wid + g];
                float bb1 = Hs[(8 * s + t + 4) * H_STR + 8 * wid + g];
                mma8(acc2, aa, bb0, bb1);
            }

            // epilogue: out = x + update * mask
            {
                const int cl = 8 * wid + 2 * t;      // chunk-local col (even)
                const int p  = pxb + cl;             // pixel 0..126 (even)
                const int py = p >> 5, pxw = p & 31;
                const float m0 = ms[p], m1 = ms[p + 1];
                const int ch = g, ch2 = g + 8;
                const float* xc0 = xs + ch  * (TPH * TPW) + (py + 1) * TPW + pxw + 1;
                const float* xc1 = xs + ch2 * (TPH * TPW) + (py + 1) * TPW + pxw + 1;
                size_t o0 = ((size_t)(b * 16 + ch)  << 18) + ((size_t)(gh0 + py) << 9) + gw0 + pxw;
                size_t o1 = ((size_t)(b * 16 + ch2) << 18) + ((size_t)(gh0 + py) << 9) + gw0 + pxw;
                float2 v0 = { xc0[0] + acc2[0] * m0, xc0[1] + acc2[1] * m1 };
                float2 v1 = { xc1[0] + acc2[2] * m0, xc1[1] + acc2[3] * m1 };
                *(float2*)(out + o0) = v0;
                *(float2*)(out + o1) = v1;
            }
        }
    }
}

extern "C" void kernel_launch(void* const* d_in, const int* in_sizes, int n_in,
                              void* d_out, int out_size)
{
    const float* x      = (const float*)d_in[0];
    const float* w0     = (const float*)d_in[1];
    const float* b0     = (const float*)d_in[2];
    const float* w1     = (const float*)d_in[3];
    const float* rand_u = (const float*)d_in[4];
    float* out = (float*)d_out;

    const int smem_bytes = SM_FLOATS * sizeof(float);   // 110080 B
    cudaFuncSetAttribute(ca_mma_kernel, cudaFuncAttributeMaxDynamicSharedMemorySize,
                         smem_bytes);
    dim3 grid(N_TILES / TILES_PER_CTA);  // 1024 CTAs
    ca_mma_kernel<<<grid, NTHR, smem_bytes>>>(x, w0, b0, w1, rand_u, out);
}